// round 9
// baseline (speedup 1.0000x reference)
#include <cuda_runtime.h>
#include <cstdint>

// Problem constants
#define BSZ  2048
#define TT   60
#define FF   89
#define HH   1024
#define G4H  4096
#define OUTN 30
// K layout: k 0..88 = W rows, k 89 = bias, k 90..95 = 0 pad, k 96..1119 = U rows.
#define KXP  96
#define KTOT 1120
#define NCHK 35
#define NRB  16            // row blocks (2048/128)
#define NHB  32            // h-col blocks (1024/32)
#define NTILES 512         // NRB * NHB
#define NCTAS 296          // 148 SMs * 2 resident CTAs

// Device-global scratch (allocation-free).
__device__ float g_hbuf[2][(size_t)BSZ * HH];
__device__ float g_c[(size_t)BSZ * HH];
__device__ float g_B[(size_t)G4H * KTOT];          // B[n][k] K-major, tf32-rounded
__device__ float g_Ax[(size_t)TT * BSZ * 128];     // packed [x_t | 1 | 0pad] per step
__device__ int   g_done[TT][NRB][NHB];             // per-tile completion flags

// ---------------- helpers ----------------
__device__ __forceinline__ uint32_t smem_u32(const void* p) {
    uint32_t a;
    asm("{ .reg .u64 t; cvta.to.shared.u64 t, %1; cvt.u32.u64 %0, t; }"
        : "=r"(a) : "l"(p));
    return a;
}
__device__ __forceinline__ float rtf32(float v) {
    unsigned r; asm("cvt.rna.tf32.f32 %0, %1;" : "=r"(r) : "f"(v));
    return __uint_as_float(r);
}
__device__ __forceinline__ void cp16(uint32_t dst, const float* src) {
    asm volatile("cp.async.cg.shared.global [%0], [%1], 16;" :: "r"(dst), "l"(src));
}
__device__ __forceinline__ void ldm_x4(uint32_t a, uint32_t& r0, uint32_t& r1,
                                       uint32_t& r2, uint32_t& r3) {
    asm volatile("ldmatrix.sync.aligned.m8n8.x4.shared.b16 {%0,%1,%2,%3}, [%4];"
                 : "=r"(r0), "=r"(r1), "=r"(r2), "=r"(r3) : "r"(a));
}
__device__ __forceinline__ void mma_tf32(float& d0, float& d1, float& d2, float& d3,
                                         uint32_t a0, uint32_t a1, uint32_t a2,
                                         uint32_t a3, uint32_t b0, uint32_t b1) {
    asm volatile(
        "mma.sync.aligned.m16n8k8.row.col.f32.tf32.tf32.f32 "
        "{%0,%1,%2,%3}, {%4,%5,%6,%7}, {%8,%9}, {%0,%1,%2,%3};"
        : "+f"(d0), "+f"(d1), "+f"(d2), "+f"(d3)
        : "r"(a0), "r"(a1), "r"(a2), "r"(a3), "r"(b0), "r"(b1));
}

// ---------------- prologue kernels ----------------
__global__ void zero_state_kernel() {
    size_t n = (size_t)BSZ * HH;
    for (size_t i = (size_t)blockIdx.x * blockDim.x + threadIdx.x; i < n;
         i += (size_t)gridDim.x * blockDim.x) {
        g_hbuf[0][i] = 0.f;
        g_c[i] = 0.f;
    }
    // Reset ALL flags every call (graph replays reuse device globals).
    for (int i = (int)(blockIdx.x * blockDim.x + threadIdx.x); i < TT * NRB * NHB;
         i += (int)(gridDim.x * blockDim.x))
        (&g_done[0][0][0])[i] = 0;
}

// B[n][k]: k<89 -> W[k][n]; k==89 -> bias[n]; k<96 -> 0; else U[k-96][n]
__global__ void pack_B_kernel(const float* __restrict__ W,
                              const float* __restrict__ U,
                              const float* __restrict__ bias) {
    size_t total = (size_t)G4H * KTOT;
    for (size_t idx = (size_t)blockIdx.x * blockDim.x + threadIdx.x; idx < total;
         idx += (size_t)gridDim.x * blockDim.x) {
        int n = (int)(idx / KTOT);
        int k = (int)(idx % KTOT);
        float v = 0.f;
        if (k < FF)       v = W[(size_t)k * G4H + n];
        else if (k == FF) v = bias[n];
        else if (k >= KXP) v = U[(size_t)(k - KXP) * G4H + n];
        g_B[idx] = rtf32(v);
    }
}

// Ax[t][m][j]: j<89 -> x[m][t][j]; j==89 -> 1; else 0 (row stride 128, 96 used)
__global__ void pack_Ax_kernel(const float* __restrict__ x) {
    size_t total = (size_t)TT * BSZ * 128;
    for (size_t idx = (size_t)blockIdx.x * blockDim.x + threadIdx.x; idx < total;
         idx += (size_t)gridDim.x * blockDim.x) {
        int j  = (int)(idx & 127);
        int tm = (int)(idx >> 7);
        int m  = tm & (BSZ - 1);
        int t  = tm >> 11;
        float v = 0.f;
        if (j < FF)       v = x[(size_t)m * (TT * FF) + t * FF + j];
        else if (j == FF) v = 1.f;
        g_Ax[idx] = rtf32(v);
    }
}

// ---------------- persistent LSTM kernel ----------------
// 296 CTAs loop over (t, tile) items t-major, stride NCTAS.
// CTA tile: 128 rows x 128 z-cols. Fine-grained dependencies: U-chunk cl
// (cl>=3) needs only producer tile (t-1, bx, cl-3); tid0 spins on its flag
// between cp.async.wait_group and the per-chunk __syncthreads (no extra
// barriers). Chunks 3..34 collectively wait all 32 flags of (t-1,bx,*),
// which also covers the hout WAR and g_c RAW before the epilogue.
#define STAGE_BYTES 32768
#define SMEM_DYN (3 * STAGE_BYTES)

__global__ __launch_bounds__(256, 2) void lstm_persistent() {
    extern __shared__ char dsm[];
    const uint32_t smem0 = smem_u32(dsm);
    const int tid  = threadIdx.x;
    const int lane = tid & 31;
    const int wid  = tid >> 5;
    const int wm   = wid >> 2;           // 0..1 : 64-row half
    const int wn   = wid & 3;            // 0..3 : 8-h-col group

    // ldmatrix lane addressing
    const int aRowL = wm * 64 + (lane & 15);
    const int aSegL = lane >> 4;
    const int bRowL = wn * 32 + ((lane >> 4) << 3) + (lane & 7);
    const int bSegL = (lane >> 3) & 1;

    const int NITEMS = TT * NTILES;
    for (int it = blockIdx.x; it < NITEMS; it += NCTAS) {
        const int t    = it >> 9;            // / 512
        const int tile = it & (NTILES - 1);
        const int bx   = tile >> 5;          // rowblock 0..15
        const int by   = tile & 31;          // h block 0..31
        const int m0   = bx * 128;
        const int hc0  = by * 32;

        const float* __restrict__ hin  = g_hbuf[t & 1];
        float*       __restrict__ hout = g_hbuf[(t + 1) & 1];

        auto load_chunk = [&](int c, int s) {
            const uint32_t aBase = smem0 + s * STAGE_BYTES;
            const uint32_t bBase = aBase + 16384;
            const int k0 = c * 32;
#pragma unroll
            for (int j = 0; j < 4; j++) {
                int idx = tid + j * 256;
                int row = idx >> 3, seg = idx & 7;
                const float* src;
                if (k0 < KXP)   // x part: W/bias columns (no h dependency)
                    src = g_Ax + ((size_t)t * BSZ + m0 + row) * 128 + k0 + seg * 4;
                else            // U part: needs h from step t-1
                    src = hin + (size_t)(m0 + row) * HH + (k0 - KXP) + seg * 4;
                cp16(aBase + row * 128 + ((seg ^ (row & 7)) << 4), src);
            }
#pragma unroll
            for (int j = 0; j < 4; j++) {
                int idx = tid + j * 256;
                int row = idx >> 3, seg = idx & 7;
                int n = (((row >> 3) & 3) << 10) + hc0 + ((row >> 5) << 3) + (row & 7);
                cp16(bBase + row * 128 + ((seg ^ (row & 7)) << 4),
                     g_B + (size_t)n * KTOT + k0 + seg * 4);
            }
            asm volatile("cp.async.commit_group;" ::: "memory");
        };

        // Chunks 0,1 are x-part: no dependency, prefetch immediately.
        load_chunk(0, 0);
        load_chunk(1, 1);

        float acc[4][4][4];   // [mfrag][gate][elem]
#pragma unroll
        for (int mf = 0; mf < 4; mf++)
#pragma unroll
            for (int g = 0; g < 4; g++)
#pragma unroll
                for (int e = 0; e < 4; e++) acc[mf][g][e] = 0.f;

        for (int ch = 0; ch < NCHK; ++ch) {
            // Chunk ch becomes resident after this wait+sync.
            asm volatile("cp.async.wait_group 1;" ::: "memory");

            // Fine-grained dependency: the chunk we're ABOUT to load (cl)
            // needs producer tile (t-1, bx, cl-3). Spin on tid0 between
            // wait_group and the barrier -> no extra synchronization.
            int cl = ch + 2;
            if (t > 0 && cl >= 3 && cl < NCHK && tid == 0) {
                const int* p = &g_done[t - 1][bx][cl - 3];
                int v;
                while (true) {
                    asm volatile("ld.acquire.gpu.global.b32 %0, [%1];"
                                 : "=r"(v) : "l"(p) : "memory");
                    if (v != 0) break;
                    __nanosleep(64);
                }
            }
            __syncthreads();

            // Load chunk cl into stage cl%3 (stage last read in iter ch-1,
            // ordered by the barrier above -> WAR safe).
            if (cl < NCHK) load_chunk(cl, cl % 3);
            else asm volatile("cp.async.commit_group;" ::: "memory");

            const uint32_t aBase = smem0 + (ch % 3) * STAGE_BYTES;
            const uint32_t bBase = aBase + 16384;
#pragma unroll
            for (int ks = 0; ks < 4; ++ks) {
                uint32_t b[2][4];
#pragma unroll
                for (int pr = 0; pr < 2; ++pr) {
                    int row = bRowL + pr * 16;
                    int seg = 2 * ks + bSegL;
                    ldm_x4(bBase + row * 128 + ((seg ^ (row & 7)) << 4),
                           b[pr][0], b[pr][1], b[pr][2], b[pr][3]);
                }
#pragma unroll
                for (int mf = 0; mf < 4; ++mf) {
                    int row = aRowL + mf * 16;
                    int seg = 2 * ks + aSegL;
                    uint32_t a0, a1, a2, a3;
                    ldm_x4(aBase + row * 128 + ((seg ^ (row & 7)) << 4),
                           a0, a1, a2, a3);
                    mma_tf32(acc[mf][0][0], acc[mf][0][1], acc[mf][0][2], acc[mf][0][3],
                             a0, a1, a2, a3, b[0][0], b[0][1]);
                    mma_tf32(acc[mf][1][0], acc[mf][1][1], acc[mf][1][2], acc[mf][1][3],
                             a0, a1, a2, a3, b[0][2], b[0][3]);
                    mma_tf32(acc[mf][2][0], acc[mf][2][1], acc[mf][2][2], acc[mf][2][3],
                             a0, a1, a2, a3, b[1][0], b[1][1]);
                    mma_tf32(acc[mf][3][0], acc[mf][3][1], acc[mf][3][2], acc[mf][3][3],
                             a0, a1, a2, a3, b[1][2], b[1][3]);
                }
            }
        }

        // Epilogue: gates + state update in registers. All 32 flags of
        // (t-1, bx, *) were waited during chunk loads -> g_c RAW and hout
        // WAR are safe here.
        {
            const int colg = hc0 + wn * 8 + 2 * (lane & 3);
#pragma unroll
            for (int mf = 0; mf < 4; ++mf) {
                const int r0 = m0 + wm * 64 + mf * 16 + (lane >> 2);
#pragma unroll
                for (int half = 0; half < 2; ++half) {
                    const int r = r0 + half * 8;
                    float2* cp2 = reinterpret_cast<float2*>(&g_c[(size_t)r * HH + colg]);
                    float2* hp2 = reinterpret_cast<float2*>(&hout[(size_t)r * HH + colg]);
                    float2 co = *cp2;
                    float cold[2] = {co.x, co.y};
                    float cn[2], hn[2];
#pragma unroll
                    for (int q = 0; q < 2; ++q) {
                        int e = half * 2 + q;
                        float iv = 1.f / (1.f + __expf(-acc[mf][0][e]));
                        float fv = 1.f / (1.f + __expf(-acc[mf][1][e]));
                        float gv = fmaxf(acc[mf][2][e], 0.f);
                        float ov = 1.f / (1.f + __expf(-acc[mf][3][e]));
                        float c2 = fv * cold[q] + iv * gv;
                        cn[q] = c2;
                        hn[q] = rtf32(ov * fmaxf(c2, 0.f));  // tf32-round for next MMA
                    }
                    *cp2 = make_float2(cn[0], cn[1]);
                    *hp2 = make_float2(hn[0], hn[1]);
                }
            }
        }

        // Publish this tile: h rows bx / cols by for step t are done.
        __threadfence();
        __syncthreads();
        if (tid == 0) {
            asm volatile("st.release.gpu.global.b32 [%0], %1;"
                         :: "l"(&g_done[t][bx][by]), "r"(1) : "memory");
        }
    }
}

// ---------------- dense head ----------------
__global__ void dense_kernel(const float* __restrict__ Wd,
                             const float* __restrict__ bd,
                             float* __restrict__ out)
{
    __shared__ float red[8][32];
    const int b = blockIdx.x;
    const int tid = threadIdx.x;
    const int o = tid & 31;
    const int sg = tid >> 5;           // 8 k-segments of 128
    const float* __restrict__ h = &g_hbuf[0][(size_t)b * HH];
    float s = 0.f;
    if (o < OUTN) {
        const int k0 = sg * 128;
#pragma unroll 4
        for (int k = k0; k < k0 + 128; ++k) s += h[k] * Wd[k * OUTN + o];
    }
    red[sg][o] = s;
    __syncthreads();
    if (tid < OUTN) {
        float a = bd[tid];
#pragma unroll
        for (int i = 0; i < 8; ++i) a += red[i][tid];
        out[(size_t)b * OUTN + tid] = a;
    }
}

extern "C" void kernel_launch(void* const* d_in, const int* in_sizes, int n_in,
                              void* d_out, int out_size)
{
    (void)in_sizes; (void)n_in; (void)out_size;
    const float* x  = (const float*)d_in[0];
    const float* W  = (const float*)d_in[1];
    const float* U  = (const float*)d_in[2];
    const float* b  = (const float*)d_in[3];
    const float* Wd = (const float*)d_in[4];
    const float* bd = (const float*)d_in[5];
    float* out = (float*)d_out;

    cudaFuncSetAttribute(lstm_persistent, cudaFuncAttributeMaxDynamicSharedMemorySize,
                         SMEM_DYN);

    zero_state_kernel<<<512, 256>>>();
    pack_B_kernel<<<2048, 256>>>(W, U, b);
    pack_Ax_kernel<<<4096, 256>>>(x);

    lstm_persistent<<<NCTAS, 256, SMEM_DYN>>>();

    dense_kernel<<<BSZ, 256>>>(Wd, bd, out);
}